// round 7
// baseline (speedup 1.0000x reference)
#include <cuda_runtime.h>
#include <math.h>

#define NMAX 8
#define LMMAX 16
#define N_SPECIES 4
#define NSEG 80000
#define CAP 32
#define OVF_CAP 4096
#define NBINS 33

static constexpr float RC = 5.0f;
static constexpr float SMOOTH_W = 0.5f;
static constexpr float PI_F = 3.14159265358979323846f;
// exp(-2 t^2) = 2^{-(S_EXP*t)^2},  S_EXP = sqrt(2*log2(e))
static constexpr float S_EXP = 1.69864363f;

// Static scratch. Layout: [0,NSEG) seg counts | [NSEG] ovf counter | [NSEG+1, +NBINS) histogram
__device__ int    d_cnt[NSEG + 1 + NBINS];
__device__ int    d_binofs[NBINS];
__device__ int    d_perm[NSEG];
__device__ float4 d_bucket[NSEG * CAP];   // (sr, x, y, z)
__device__ float  d_blfc[NSEG * CAP];     // log2(fc)
__device__ float4 d_ovf_data[OVF_CAP];
__device__ float  d_ovf_lfc[OVF_CAP];
__device__ int    d_ovf_seg[OVF_CAP];

__device__ __forceinline__ float ex2(float a) {
    float y;
    asm("ex2.approx.ftz.f32 %0, %1;" : "=f"(y) : "f"(a));
    return y;
}

__device__ __forceinline__ float cutoff_branchless(float r) {
    float t = __saturatef((r - (RC - SMOOTH_W)) * (1.0f / SMOOTH_W));
    return 0.5f * (1.0f + __cosf(PI_F * t));
}

__device__ __forceinline__ void sph_harm(float x, float y, float zd, float* Y) {
    float x2 = x * x, y2 = y * y, z2 = zd * zd;
    Y[0]  = 0.28209479177387814f;
    Y[1]  = 0.4886025119029199f * y;
    Y[2]  = 0.4886025119029199f * zd;
    Y[3]  = 0.4886025119029199f * x;
    Y[4]  = 1.0925484305920792f * x * y;
    Y[5]  = 1.0925484305920792f * y * zd;
    Y[6]  = 0.31539156525252005f * (2.0f * z2 - x2 - y2);
    Y[7]  = 1.0925484305920792f * x * zd;
    Y[8]  = 0.5462742152960396f * (x2 - y2);
    Y[9]  = 0.5900435899266435f * y * (3.0f * x2 - y2);
    Y[10] = 2.890611442640554f * x * y * zd;
    Y[11] = 0.4570457994644658f * y * (4.0f * z2 - x2 - y2);
    Y[12] = 0.3731763325901154f * zd * (2.0f * z2 - 3.0f * x2 - 3.0f * y2);
    Y[13] = 0.4570457994644658f * x * (4.0f * z2 - x2 - y2);
    Y[14] = 1.445305721320277f * zd * (x2 - y2);
    Y[15] = 0.5900435899266435f * x * (x2 - 3.0f * y2);
}

__global__ __launch_bounds__(256)
void fill_kernel(const float* __restrict__ dist,
                 const float* __restrict__ dirs,
                 const int* __restrict__ z,
                 const int* __restrict__ idx_i,
                 const int* __restrict__ idx_j,
                 int J)
{
    int e = blockIdx.x * blockDim.x + threadIdx.x;
    if (e >= J) return;
    float r  = __ldg(dist + e);
    float x  = __ldg(dirs + 3 * e + 0);
    float y  = __ldg(dirs + 3 * e + 1);
    float zd = __ldg(dirs + 3 * e + 2);
    int seg = __ldg(z + __ldg(idx_j + e)) + N_SPECIES * __ldg(idx_i + e);

    float fc  = cutoff_branchless(r);
    float lfc = __log2f(fc);               // -inf when fc == 0 -> ex2 -> 0 (exact)
    float4 v  = make_float4(S_EXP * r, x, y, zd);

    int pos = atomicAdd(&d_cnt[seg], 1);
    if (pos < CAP) {
        d_bucket[seg * CAP + pos] = v;
        d_blfc[seg * CAP + pos]   = lfc;
    } else {
        int op = atomicAdd(&d_cnt[NSEG], 1);
        if (op < OVF_CAP) {
            d_ovf_data[op] = v; d_ovf_lfc[op] = lfc; d_ovf_seg[op] = seg;
        }
    }
}

// ---- counting sort of segments by (clamped) count --------------------------
__global__ __launch_bounds__(256)
void hist_kernel() {
    __shared__ int sh[NBINS];
    if (threadIdx.x < NBINS) sh[threadIdx.x] = 0;
    __syncthreads();
    int i = blockIdx.x * blockDim.x + threadIdx.x;
    if (i < NSEG) {
        int c = d_cnt[i]; if (c > CAP) c = CAP;
        atomicAdd(&sh[c], 1);
    }
    __syncthreads();
    if (threadIdx.x < NBINS && sh[threadIdx.x] > 0)
        atomicAdd(&d_cnt[NSEG + 1 + threadIdx.x], sh[threadIdx.x]);
}

__global__ void prefix_kernel() {
    if (threadIdx.x == 0) {
        int s = 0;
        for (int c = 0; c < NBINS; c++) {
            d_binofs[c] = s;
            s += d_cnt[NSEG + 1 + c];
        }
    }
}

__global__ __launch_bounds__(256)
void scatter_kernel() {
    __shared__ int sh_cnt[NBINS];
    __shared__ int sh_base[NBINS];
    if (threadIdx.x < NBINS) sh_cnt[threadIdx.x] = 0;
    __syncthreads();
    int i = blockIdx.x * blockDim.x + threadIdx.x;
    int c = 0, rank = 0;
    if (i < NSEG) {
        c = d_cnt[i]; if (c > CAP) c = CAP;
        rank = atomicAdd(&sh_cnt[c], 1);
    }
    __syncthreads();
    if (threadIdx.x < NBINS && sh_cnt[threadIdx.x] > 0)
        sh_base[threadIdx.x] = atomicAdd(&d_binofs[threadIdx.x], sh_cnt[threadIdx.x]);
    __syncthreads();
    if (i < NSEG)
        d_perm[sh_base[c] + rank] = i;
}
// ---------------------------------------------------------------------------

// Accumulate one edge for two consecutive n values. R = 2^(lfc - t^2).
__device__ __forceinline__ void accum_edge(float sr, float x, float y, float zd,
                                           float lfc, const float cs[4][2],
                                           float* __restrict__ acc0,
                                           float* __restrict__ acc1)
{
    float Ra[4], Rb[4];
#pragma unroll
    for (int l = 0; l < 4; l++) {
        float ta = sr - cs[l][0];
        float tb = sr - cs[l][1];
        Ra[l] = ex2(fmaf(-ta, ta, lfc));
        Rb[l] = ex2(fmaf(-tb, tb, lfc));
    }

    float Y[LMMAX];
    sph_harm(x, y, zd, Y);

    const int LTAB[LMMAX] = {0,1,1,1,2,2,2,2,2,3,3,3,3,3,3,3};
#pragma unroll
    for (int lm = 0; lm < LMMAX; lm++) {
        int l = LTAB[lm];
        acc0[lm] += Ra[l] * Y[lm];
        acc1[lm] += Rb[l] * Y[lm];
    }
}

// One thread per (sorted-segment, n-pair). Warp spans 8 segments of ~equal count.
__global__ __launch_bounds__(256)
void gather_kernel(const float* __restrict__ centers,
                   float* __restrict__ out)
{
    int tid = blockIdx.x * blockDim.x + threadIdx.x;
    if (tid >= NSEG * 4) return;
    int seg = d_perm[tid >> 2];
    int np  = tid & 3;          // n0 = 2*np, n1 = 2*np+1

    float cs[4][2];
#pragma unroll
    for (int l = 0; l < 4; l++) {
        cs[l][0] = S_EXP * __ldg(centers + l * NMAX + 2 * np + 0);
        cs[l][1] = S_EXP * __ldg(centers + l * NMAX + 2 * np + 1);
    }

    float acc0[LMMAX], acc1[LMMAX];
#pragma unroll
    for (int i = 0; i < LMMAX; i++) { acc0[i] = 0.0f; acc1[i] = 0.0f; }

    int cnt_raw = d_cnt[seg];
    int cnt = cnt_raw > CAP ? CAP : cnt_raw;
    const float4* bk = d_bucket + seg * CAP;
    const float*  bf = d_blfc   + seg * CAP;

    for (int k = 0; k < cnt; k++) {
        float4 v  = bk[k];
        float lfc = bf[k];
        accum_edge(v.x, v.y, v.z, v.w, lfc, cs, acc0, acc1);
    }

    if (cnt_raw > CAP) {        // astronomically rare
        int novf = d_cnt[NSEG];
        if (novf > OVF_CAP) novf = OVF_CAP;
        for (int t = 0; t < novf; t++) {
            if (d_ovf_seg[t] == seg) {
                float4 v = d_ovf_data[t];
                accum_edge(v.x, v.y, v.z, v.w, d_ovf_lfc[t], cs, acc0, acc1);
            }
        }
    }

    float4* o = (float4*)(out + (size_t)seg * (NMAX * LMMAX) + np * 2 * LMMAX);
    o[0] = make_float4(acc0[0],  acc0[1],  acc0[2],  acc0[3]);
    o[1] = make_float4(acc0[4],  acc0[5],  acc0[6],  acc0[7]);
    o[2] = make_float4(acc0[8],  acc0[9],  acc0[10], acc0[11]);
    o[3] = make_float4(acc0[12], acc0[13], acc0[14], acc0[15]);
    o[4] = make_float4(acc1[0],  acc1[1],  acc1[2],  acc1[3]);
    o[5] = make_float4(acc1[4],  acc1[5],  acc1[6],  acc1[7]);
    o[6] = make_float4(acc1[8],  acc1[9],  acc1[10], acc1[11]);
    o[7] = make_float4(acc1[12], acc1[13], acc1[14], acc1[15]);
}

extern "C" void kernel_launch(void* const* d_in, const int* in_sizes, int n_in,
                              void* d_out, int out_size) {
    const float* dist    = (const float*)d_in[0];
    const float* dirs    = (const float*)d_in[1];
    const float* centers = (const float*)d_in[2];
    const int*   z       = (const int*)d_in[3];
    const int*   idx_i   = (const int*)d_in[4];
    const int*   idx_j   = (const int*)d_in[5];
    float*       out     = (float*)d_out;

    int J = in_sizes[0];

    void* cnt_ptr = nullptr;
    cudaGetSymbolAddress(&cnt_ptr, d_cnt);
    cudaMemsetAsync(cnt_ptr, 0, (NSEG + 1 + NBINS) * sizeof(int));

    fill_kernel<<<(J + 255) / 256, 256>>>(dist, dirs, z, idx_i, idx_j, J);
    hist_kernel<<<(NSEG + 255) / 256, 256>>>();
    prefix_kernel<<<1, 32>>>();
    scatter_kernel<<<(NSEG + 255) / 256, 256>>>();
    gather_kernel<<<(NSEG * 4 + 255) / 256, 256>>>(centers, out);
}

// round 8
// speedup vs baseline: 1.0825x; 1.0825x over previous
#include <cuda_runtime.h>
#include <math.h>

#define NMAX 8
#define LMMAX 16
#define N_SPECIES 4
#define NSEG 80000
#define CAP 32
#define OVF_CAP 4096
#define NBINS 33
#define NWARPS 10000            // NSEG*4/32
#define WSTRIDE 2503            // coprime with NWARPS

static constexpr float RC = 5.0f;
static constexpr float SMOOTH_W = 0.5f;
static constexpr float PI_F = 3.14159265358979323846f;
static constexpr float S_EXP = 1.69864363f;   // sqrt(2*log2(e))

// Scratch layout inside d_scratch:
//   [0, NSEG)               per-segment counts
//   [NSEG]                  overflow counter
//   [NSEG+1, NSEG+1+33)     global count histogram
//   [NSEG+34, NSEG+34+33)   per-bin relative offsets (scatter)
__device__ int    d_scratch[NSEG + 1 + 2 * NBINS];
__device__ int    d_perm[NSEG];
__device__ float4 d_bucket[NSEG * CAP];   // (sr, x, y, z)
__device__ float  d_blfc[NSEG * CAP];     // log2(fc)
__device__ float4 d_ovf_data[OVF_CAP];
__device__ float  d_ovf_lfc[OVF_CAP];
__device__ int    d_ovf_seg[OVF_CAP];

__device__ __forceinline__ float ex2(float a) {
    float y;
    asm("ex2.approx.ftz.f32 %0, %1;" : "=f"(y) : "f"(a));
    return y;
}

__device__ __forceinline__ float cutoff_branchless(float r) {
    float t = __saturatef((r - (RC - SMOOTH_W)) * (1.0f / SMOOTH_W));
    return 0.5f * (1.0f + __cosf(PI_F * t));
}

__device__ __forceinline__ void sph_harm(float x, float y, float zd, float* Y) {
    float x2 = x * x, y2 = y * y, z2 = zd * zd;
    Y[0]  = 0.28209479177387814f;
    Y[1]  = 0.4886025119029199f * y;
    Y[2]  = 0.4886025119029199f * zd;
    Y[3]  = 0.4886025119029199f * x;
    Y[4]  = 1.0925484305920792f * x * y;
    Y[5]  = 1.0925484305920792f * y * zd;
    Y[6]  = 0.31539156525252005f * (2.0f * z2 - x2 - y2);
    Y[7]  = 1.0925484305920792f * x * zd;
    Y[8]  = 0.5462742152960396f * (x2 - y2);
    Y[9]  = 0.5900435899266435f * y * (3.0f * x2 - y2);
    Y[10] = 2.890611442640554f * x * y * zd;
    Y[11] = 0.4570457994644658f * y * (4.0f * z2 - x2 - y2);
    Y[12] = 0.3731763325901154f * zd * (2.0f * z2 - 3.0f * x2 - 3.0f * y2);
    Y[13] = 0.4570457994644658f * x * (4.0f * z2 - x2 - y2);
    Y[14] = 1.445305721320277f * zd * (x2 - y2);
    Y[15] = 0.5900435899266435f * x * (x2 - 3.0f * y2);
}

__global__ __launch_bounds__(256)
void fill_kernel(const float* __restrict__ dist,
                 const float* __restrict__ dirs,
                 const int* __restrict__ z,
                 const int* __restrict__ idx_i,
                 const int* __restrict__ idx_j,
                 int J)
{
    int e = blockIdx.x * blockDim.x + threadIdx.x;
    if (e >= J) return;
    float r  = __ldg(dist + e);
    float x  = __ldg(dirs + 3 * e + 0);
    float y  = __ldg(dirs + 3 * e + 1);
    float zd = __ldg(dirs + 3 * e + 2);
    int seg = __ldg(z + __ldg(idx_j + e)) + N_SPECIES * __ldg(idx_i + e);

    float lfc = __log2f(cutoff_branchless(r));   // -inf when fc==0 -> ex2 -> 0
    float4 v  = make_float4(S_EXP * r, x, y, zd);

    int pos = atomicAdd(&d_scratch[seg], 1);
    if (pos < CAP) {
        d_bucket[seg * CAP + pos] = v;
        d_blfc[seg * CAP + pos]   = lfc;
    } else {
        int op = atomicAdd(&d_scratch[NSEG], 1);
        if (op < OVF_CAP) {
            d_ovf_data[op] = v; d_ovf_lfc[op] = lfc; d_ovf_seg[op] = seg;
        }
    }
}

__global__ __launch_bounds__(256)
void hist_kernel() {
    __shared__ int sh[NBINS];
    if (threadIdx.x < NBINS) sh[threadIdx.x] = 0;
    __syncthreads();
    int i = blockIdx.x * blockDim.x + threadIdx.x;
    if (i < NSEG) {
        int c = d_scratch[i]; if (c > CAP) c = CAP;
        atomicAdd(&sh[c], 1);
    }
    __syncthreads();
    if (threadIdx.x < NBINS && sh[threadIdx.x] > 0)
        atomicAdd(&d_scratch[NSEG + 1 + threadIdx.x], sh[threadIdx.x]);
}

// Sort segments DESCENDING by count. Bin bases computed inline (suffix sum of
// the global histogram); single relative-offset atomic phase. No prefix kernel.
__global__ __launch_bounds__(256)
void scatter_kernel() {
    __shared__ int sh_cnt[NBINS];
    __shared__ int sh_base[NBINS];
    if (threadIdx.x < NBINS) sh_cnt[threadIdx.x] = 0;
    __syncthreads();
    int i = blockIdx.x * blockDim.x + threadIdx.x;
    int c = 0, rank = 0;
    if (i < NSEG) {
        c = d_scratch[i]; if (c > CAP) c = CAP;
        rank = atomicAdd(&sh_cnt[c], 1);
    }
    __syncthreads();
    if (threadIdx.x < NBINS) {
        int base = 0;                                  // descending: bins > c first
        for (int c2 = threadIdx.x + 1; c2 < NBINS; c2++)
            base += d_scratch[NSEG + 1 + c2];
        int rel = 0;
        if (sh_cnt[threadIdx.x] > 0)
            rel = atomicAdd(&d_scratch[NSEG + 1 + NBINS + threadIdx.x], sh_cnt[threadIdx.x]);
        sh_base[threadIdx.x] = base + rel;
    }
    __syncthreads();
    if (i < NSEG)
        d_perm[sh_base[c] + rank] = i;
}

// R = 2^(lfc - t^2) for two consecutive n values; accumulate into acc0/acc1.
__device__ __forceinline__ void accum_edge(float sr, float x, float y, float zd,
                                           float lfc, const float cs[4][2],
                                           float* __restrict__ acc0,
                                           float* __restrict__ acc1)
{
    float Ra[4], Rb[4];
#pragma unroll
    for (int l = 0; l < 4; l++) {
        float ta = sr - cs[l][0];
        float tb = sr - cs[l][1];
        Ra[l] = ex2(fmaf(-ta, ta, lfc));
        Rb[l] = ex2(fmaf(-tb, tb, lfc));
    }

    float Y[LMMAX];
    sph_harm(x, y, zd, Y);

    const int LTAB[LMMAX] = {0,1,1,1,2,2,2,2,2,3,3,3,3,3,3,3};
#pragma unroll
    for (int lm = 0; lm < LMMAX; lm++) {
        int l = LTAB[lm];
        acc0[lm] += Ra[l] * Y[lm];
        acc1[lm] += Rb[l] * Y[lm];
    }
}

// Warps are count-homogeneous (8 consecutive sorted slots); blocks are
// count-heterogeneous (coprime warp shuffle) -> no heavy tail wave.
__global__ __launch_bounds__(256)
void gather_kernel(const float* __restrict__ centers,
                   float* __restrict__ out)
{
    int tid = blockIdx.x * blockDim.x + threadIdx.x;
    if (tid >= NSEG * 4) return;
    int w    = tid >> 5;
    int lane = tid & 31;
    int wp   = (int)(((long long)w * WSTRIDE) % NWARPS);
    int slot = wp * 8 + (lane >> 2);
    int seg  = d_perm[slot];
    int np   = lane & 3;                 // n0 = 2*np, n1 = 2*np+1

    float cs[4][2];
#pragma unroll
    for (int l = 0; l < 4; l++) {
        cs[l][0] = S_EXP * __ldg(centers + l * NMAX + 2 * np + 0);
        cs[l][1] = S_EXP * __ldg(centers + l * NMAX + 2 * np + 1);
    }

    float acc0[LMMAX], acc1[LMMAX];
#pragma unroll
    for (int i = 0; i < LMMAX; i++) { acc0[i] = 0.0f; acc1[i] = 0.0f; }

    int cnt_raw = d_scratch[seg];
    int cnt = cnt_raw > CAP ? CAP : cnt_raw;
    const float4* bk = d_bucket + seg * CAP;
    const float*  bf = d_blfc   + seg * CAP;

#pragma unroll 2
    for (int k = 0; k < cnt; k++) {
        float4 v  = __ldg(bk + k);
        float lfc = __ldg(bf + k);
        accum_edge(v.x, v.y, v.z, v.w, lfc, cs, acc0, acc1);
    }

    if (cnt_raw > CAP) {                 // astronomically rare
        int novf = d_scratch[NSEG];
        if (novf > OVF_CAP) novf = OVF_CAP;
        for (int t = 0; t < novf; t++) {
            if (d_ovf_seg[t] == seg) {
                float4 v = d_ovf_data[t];
                accum_edge(v.x, v.y, v.z, v.w, d_ovf_lfc[t], cs, acc0, acc1);
            }
        }
    }

    float4* o = (float4*)(out + (size_t)seg * (NMAX * LMMAX) + np * 2 * LMMAX);
    o[0] = make_float4(acc0[0],  acc0[1],  acc0[2],  acc0[3]);
    o[1] = make_float4(acc0[4],  acc0[5],  acc0[6],  acc0[7]);
    o[2] = make_float4(acc0[8],  acc0[9],  acc0[10], acc0[11]);
    o[3] = make_float4(acc0[12], acc0[13], acc0[14], acc0[15]);
    o[4] = make_float4(acc1[0],  acc1[1],  acc1[2],  acc1[3]);
    o[5] = make_float4(acc1[4],  acc1[5],  acc1[6],  acc1[7]);
    o[6] = make_float4(acc1[8],  acc1[9],  acc1[10], acc1[11]);
    o[7] = make_float4(acc1[12], acc1[13], acc1[14], acc1[15]);
}

extern "C" void kernel_launch(void* const* d_in, const int* in_sizes, int n_in,
                              void* d_out, int out_size) {
    const float* dist    = (const float*)d_in[0];
    const float* dirs    = (const float*)d_in[1];
    const float* centers = (const float*)d_in[2];
    const int*   z       = (const int*)d_in[3];
    const int*   idx_i   = (const int*)d_in[4];
    const int*   idx_j   = (const int*)d_in[5];
    float*       out     = (float*)d_out;

    int J = in_sizes[0];

    void* scratch_ptr = nullptr;
    cudaGetSymbolAddress(&scratch_ptr, d_scratch);
    cudaMemsetAsync(scratch_ptr, 0, (NSEG + 1 + 2 * NBINS) * sizeof(int));

    fill_kernel<<<(J + 255) / 256, 256>>>(dist, dirs, z, idx_i, idx_j, J);
    hist_kernel<<<(NSEG + 255) / 256, 256>>>();
    scatter_kernel<<<(NSEG + 255) / 256, 256>>>();
    gather_kernel<<<(NSEG * 4 + 255) / 256, 256>>>(centers, out);
}